// round 4
// baseline (speedup 1.0000x reference)
#include <cuda_runtime.h>
#include <cstdint>

#define SS 4096
#define DK 64
#define DM 512
#define HH 8
#define BB 2
#define BH 16

// Scratch (static device globals — no runtime allocation)
__device__ float g_Q[BH*SS*DK];   // tf32-rounded, pre-scaled by log2(e)/8
__device__ float g_K[BH*SS*DK];   // tf32-rounded
__device__ float g_V[BH*SS*DK];   // tf32-rounded
__device__ float g_O[BB*SS*DM];   // fp32 attention output (concat layout)

__device__ __forceinline__ uint32_t f2tf(float f) {
    uint32_t u; asm("cvt.rna.tf32.f32 %0, %1;" : "=r"(u) : "f"(f)); return u;
}

// D += A(16x8,row) * B(8x8,col), tf32 inputs, f32 accum
__device__ __forceinline__ void mma8(float* d, const uint32_t* a, const uint32_t* b) {
    asm volatile("mma.sync.aligned.m16n8k8.row.col.f32.tf32.tf32.f32 "
        "{%0,%1,%2,%3}, {%4,%5,%6,%7}, {%8,%9}, {%0,%1,%2,%3};"
        : "+f"(d[0]), "+f"(d[1]), "+f"(d[2]), "+f"(d[3])
        : "r"(a[0]), "r"(a[1]), "r"(a[2]), "r"(a[3]), "r"(b[0]), "r"(b[1]));
}

__device__ __forceinline__ void cpa16(uint32_t dst, const void* src) {
    asm volatile("cp.async.cg.shared.global [%0], [%1], 16;" :: "r"(dst), "l"(src));
}

// ================= Projection GEMM: 128x128x16, 256 thr, warp tile 64x32 =================
#define PBM 128
#define PBN 128
#define PBK 16
#define AST 20
#define BST 136

__global__ __launch_bounds__(256) void qkv_kernel(const float* __restrict__ X,
                                                  const float* __restrict__ Wq,
                                                  const float* __restrict__ Wk,
                                                  const float* __restrict__ Wv)
{
    __shared__ uint32_t As[PBM*AST];
    __shared__ uint32_t Bs[PBK*BST];
    const int tid = threadIdx.x;
    const int nb = blockIdx.x, mb = blockIdx.y;
    const int proj = nb >> 2;
    const float* W = (proj==0) ? Wq : (proj==1) ? Wk : Wv;
    float* OutB   = (proj==0) ? g_Q : (proj==1) ? g_K : g_V;
    const int cb = (nb & 3) * PBN;

    const int warp = tid >> 5, lane = tid & 31;
    const int g = lane >> 2, c = lane & 3;
    const int wm = (warp & 1) * 64, wn = (warp >> 1) * 32;

    float acc[4][4][4];
    #pragma unroll
    for (int i=0;i<4;i++)
        #pragma unroll
        for (int j=0;j<4;j++)
            #pragma unroll
            for (int k=0;k<4;k++) acc[i][j][k] = 0.f;

    const int la_row = tid >> 1,  la_c = (tid & 1) * 8;
    const int lb_row = tid >> 4,  lb_c = (tid & 15) * 8;
    const float* Ap = X + (size_t)(mb*PBM + la_row)*DM + la_c;
    const float* Bp = W + (size_t)lb_row*DM + cb + lb_c;

    float4 ra0 = *(const float4*)(Ap);
    float4 ra1 = *(const float4*)(Ap + 4);
    float4 rb0 = *(const float4*)(Bp);
    float4 rb1 = *(const float4*)(Bp + 4);

    for (int k0 = 0; k0 < DM; k0 += PBK) {
        uint32_t* as = As + la_row*AST + la_c;
        as[0]=f2tf(ra0.x); as[1]=f2tf(ra0.y); as[2]=f2tf(ra0.z); as[3]=f2tf(ra0.w);
        as[4]=f2tf(ra1.x); as[5]=f2tf(ra1.y); as[6]=f2tf(ra1.z); as[7]=f2tf(ra1.w);
        uint32_t* bs = Bs + lb_row*BST + lb_c;
        bs[0]=f2tf(rb0.x); bs[1]=f2tf(rb0.y); bs[2]=f2tf(rb0.z); bs[3]=f2tf(rb0.w);
        bs[4]=f2tf(rb1.x); bs[5]=f2tf(rb1.y); bs[6]=f2tf(rb1.z); bs[7]=f2tf(rb1.w);
        __syncthreads();
        if (k0 + PBK < DM) {
            ra0 = *(const float4*)(Ap + k0 + PBK);
            ra1 = *(const float4*)(Ap + k0 + PBK + 4);
            rb0 = *(const float4*)(Bp + (size_t)(k0+PBK)*DM);
            rb1 = *(const float4*)(Bp + (size_t)(k0+PBK)*DM + 4);
        }
        #pragma unroll
        for (int ks = 0; ks < 2; ks++) {
            uint32_t a[4][4];
            #pragma unroll
            for (int mi=0; mi<4; mi++) {
                const uint32_t* ap = As + (wm + mi*16 + g)*AST + ks*8 + c;
                a[mi][0] = ap[0];
                a[mi][1] = ap[8*AST];
                a[mi][2] = ap[4];
                a[mi][3] = ap[8*AST + 4];
            }
            #pragma unroll
            for (int ni=0; ni<4; ni++) {
                uint32_t b[2];
                const uint32_t* bp = Bs + (ks*8 + c)*BST + wn + ni*8 + g;
                b[0] = bp[0];
                b[1] = bp[4*BST];
                #pragma unroll
                for (int mi=0; mi<4; mi++) mma8(acc[mi][ni], a[mi], b);
            }
        }
        __syncthreads();
    }

    // Q gets 1/8 (softmax scale) * log2(e) folded in (attention runs in exp2 domain)
    const float qscale = (proj == 0) ? 0.125f * 1.44269504088896f : 1.0f;
    #pragma unroll
    for (int mi=0; mi<4; mi++) {
        #pragma unroll
        for (int h=0; h<2; h++) {
            int gm = mb*PBM + wm + mi*16 + g + h*8;
            int b = gm >> 12, s = gm & (SS-1);
            #pragma unroll
            for (int ni=0; ni<4; ni++) {
                int wc = cb + wn + ni*8 + 2*c;
                int hd = wc >> 6, d = wc & 63;
                float v0 = acc[mi][ni][h*2+0]*qscale;
                float v1 = acc[mi][ni][h*2+1]*qscale;
                float* o = OutB + (((size_t)(b*HH + hd)*SS) + s)*DK + d;
                o[0] = __uint_as_float(f2tf(v0));
                o[1] = __uint_as_float(f2tf(v1));
            }
        }
    }
}

__global__ __launch_bounds__(256) void oproj_kernel(const float* __restrict__ Wo,
                                                    float* __restrict__ Out)
{
    __shared__ uint32_t As[PBM*AST];
    __shared__ uint32_t Bs[PBK*BST];
    const int tid = threadIdx.x;
    const int nb = blockIdx.x, mb = blockIdx.y;
    const int cb = nb * PBN;

    const int warp = tid >> 5, lane = tid & 31;
    const int g = lane >> 2, c = lane & 3;
    const int wm = (warp & 1) * 64, wn = (warp >> 1) * 32;

    float acc[4][4][4];
    #pragma unroll
    for (int i=0;i<4;i++)
        #pragma unroll
        for (int j=0;j<4;j++)
            #pragma unroll
            for (int k=0;k<4;k++) acc[i][j][k] = 0.f;

    const int la_row = tid >> 1,  la_c = (tid & 1) * 8;
    const int lb_row = tid >> 4,  lb_c = (tid & 15) * 8;
    const float* Ap = g_O + (size_t)(mb*PBM + la_row)*DM + la_c;
    const float* Bp = Wo + (size_t)lb_row*DM + cb + lb_c;

    float4 ra0 = *(const float4*)(Ap);
    float4 ra1 = *(const float4*)(Ap + 4);
    float4 rb0 = *(const float4*)(Bp);
    float4 rb1 = *(const float4*)(Bp + 4);

    for (int k0 = 0; k0 < DM; k0 += PBK) {
        uint32_t* as = As + la_row*AST + la_c;
        as[0]=f2tf(ra0.x); as[1]=f2tf(ra0.y); as[2]=f2tf(ra0.z); as[3]=f2tf(ra0.w);
        as[4]=f2tf(ra1.x); as[5]=f2tf(ra1.y); as[6]=f2tf(ra1.z); as[7]=f2tf(ra1.w);
        uint32_t* bs = Bs + lb_row*BST + lb_c;
        bs[0]=f2tf(rb0.x); bs[1]=f2tf(rb0.y); bs[2]=f2tf(rb0.z); bs[3]=f2tf(rb0.w);
        bs[4]=f2tf(rb1.x); bs[5]=f2tf(rb1.y); bs[6]=f2tf(rb1.z); bs[7]=f2tf(rb1.w);
        __syncthreads();
        if (k0 + PBK < DM) {
            ra0 = *(const float4*)(Ap + k0 + PBK);
            ra1 = *(const float4*)(Ap + k0 + PBK + 4);
            rb0 = *(const float4*)(Bp + (size_t)(k0+PBK)*DM);
            rb1 = *(const float4*)(Bp + (size_t)(k0+PBK)*DM + 4);
        }
        #pragma unroll
        for (int ks = 0; ks < 2; ks++) {
            uint32_t a[4][4];
            #pragma unroll
            for (int mi=0; mi<4; mi++) {
                const uint32_t* ap = As + (wm + mi*16 + g)*AST + ks*8 + c;
                a[mi][0] = ap[0];
                a[mi][1] = ap[8*AST];
                a[mi][2] = ap[4];
                a[mi][3] = ap[8*AST + 4];
            }
            #pragma unroll
            for (int ni=0; ni<4; ni++) {
                uint32_t b[2];
                const uint32_t* bp = Bs + (ks*8 + c)*BST + wn + ni*8 + g;
                b[0] = bp[0];
                b[1] = bp[4*BST];
                #pragma unroll
                for (int mi=0; mi<4; mi++) mma8(acc[mi][ni], a[mi], b);
            }
        }
        __syncthreads();
    }

    #pragma unroll
    for (int mi=0; mi<4; mi++) {
        #pragma unroll
        for (int h=0; h<2; h++) {
            int gm = mb*PBM + wm + mi*16 + g + h*8;
            #pragma unroll
            for (int ni=0; ni<4; ni++) {
                float2 v = { acc[mi][ni][h*2+0], acc[mi][ni][h*2+1] };
                *(float2*)(Out + (size_t)gm*DM + cb + wn + ni*8 + 2*c) = v;
            }
        }
    }
}

// ================= Flash attention v2: 256 thr (8 warps x 16 rows), cp.async dbl-buffer ====
#define TST 68                       // padded row stride (words) for K/V tiles
#define TILE_W (64*TST)              // one K or V buffer
#define SMW_TOTAL (4*TILE_W)         // K0,K1,V0,V1 = 17408 words = 69632 bytes

__global__ __launch_bounds__(256, 2) void attn_kernel()
{
    extern __shared__ uint32_t smu[];
    const int tid = threadIdx.x;
    const int warp = tid >> 5, lane = tid & 31;
    const int g = lane >> 2, c = lane & 3;
    const int wm = warp * 16;
    const int qt = blockIdx.x;   // 0..31
    const int bh = blockIdx.y;   // 0..15

    const uint32_t* Qg = (const uint32_t*)g_Q + ((size_t)bh*SS + qt*128)*DK;
    const uint32_t* Kg = (const uint32_t*)g_K + (size_t)bh*SS*DK;
    const uint32_t* Vg = (const uint32_t*)g_V + (size_t)bh*SS*DK;

    // ---- Stage Q through smem once, pull fragments into registers ----
    #pragma unroll
    for (int i = 0; i < 8; i++) {
        int e = tid + i*256;
        int row = e >> 4, c4 = (e & 15) * 4;
        *(uint4*)(smu + row*TST + c4) = *(const uint4*)(Qg + row*DK + c4);
    }
    __syncthreads();
    uint32_t q[8][4];
    #pragma unroll
    for (int kf = 0; kf < 8; kf++) {
        const uint32_t* qp = smu + (wm + g)*TST + kf*8 + c;
        q[kf][0] = qp[0];
        q[kf][1] = qp[8*TST];
        q[kf][2] = qp[4];
        q[kf][3] = qp[8*TST + 4];
    }
    __syncthreads();   // Q reads done before cp.async overwrites the region

    uint32_t kb0 = (uint32_t)__cvta_generic_to_shared(smu);
    const int row_i = tid >> 4, c4_i = (tid & 15) * 4;   // per-thread load slot

    // issue one 64-key K+V tile into buffer b
    auto issue = [&](int kt, int b) {
        uint32_t kdst = kb0 + (uint32_t)(b*TILE_W)*4;
        uint32_t vdst = kb0 + (uint32_t)((2+b)*TILE_W)*4;
        const uint32_t* ks = Kg + (size_t)(kt*64)*DK;
        const uint32_t* vs = Vg + (size_t)(kt*64)*DK;
        #pragma unroll
        for (int i = 0; i < 4; i++) {
            int row = row_i + i*16;
            cpa16(kdst + (uint32_t)(row*TST + c4_i)*4, ks + (size_t)row*DK + c4_i);
            cpa16(vdst + (uint32_t)(row*TST + c4_i)*4, vs + (size_t)row*DK + c4_i);
        }
        asm volatile("cp.async.commit_group;" ::: "memory");
    };

    issue(0, 0);

    float o[8][4];
    float mr[2] = {-1e30f, -1e30f}, lr[2] = {0.f, 0.f};
    #pragma unroll
    for (int n=0;n<8;n++)
        #pragma unroll
        for (int k=0;k<4;k++) o[n][k]=0.f;

    const int src0 = (lane & 28) | (c >> 1);   // 4g + c/2
    const bool odd = lane & 1;

    for (int kt = 0; kt < SS/64; kt++) {
        const int cur = kt & 1;
        if (kt < SS/64 - 1) {
            issue(kt+1, cur^1);
            asm volatile("cp.async.wait_group 1;" ::: "memory");
        } else {
            asm volatile("cp.async.wait_group 0;" ::: "memory");
        }
        __syncthreads();

        const uint32_t* Ks = smu + cur*TILE_W;
        const uint32_t* Vs = smu + (2+cur)*TILE_W;

        // ---- S = Q K^T (log2-domain, Q pre-scaled) ----
        float s[8][4];
        #pragma unroll
        for (int n=0;n<8;n++)
            #pragma unroll
            for (int k=0;k<4;k++) s[n][k]=0.f;

        #pragma unroll
        for (int kf = 0; kf < 8; kf++) {
            #pragma unroll
            for (int n = 0; n < 8; n++) {
                uint32_t b[2];
                const uint32_t* kp = Ks + (n*8 + g)*TST + kf*8 + c;
                b[0] = kp[0];
                b[1] = kp[4];
                mma8(s[n], q[kf], b);
            }
        }

        // ---- online softmax (exp2) ----
        #pragma unroll
        for (int h = 0; h < 2; h++) {
            float mx = -1e30f;
            #pragma unroll
            for (int n=0;n<8;n++) mx = fmaxf(mx, fmaxf(s[n][h*2], s[n][h*2+1]));
            mx = fmaxf(mx, __shfl_xor_sync(0xffffffffu, mx, 1));
            mx = fmaxf(mx, __shfl_xor_sync(0xffffffffu, mx, 2));
            float mnew = fmaxf(mr[h], mx);
            float alpha = exp2f(mr[h] - mnew);
            mr[h] = mnew;
            float rs = 0.f;
            #pragma unroll
            for (int n=0;n<8;n++) {
                float p0 = exp2f(s[n][h*2]   - mnew);
                float p1 = exp2f(s[n][h*2+1] - mnew);
                s[n][h*2] = p0; s[n][h*2+1] = p1;
                rs += p0 + p1;
            }
            rs += __shfl_xor_sync(0xffffffffu, rs, 1);
            rs += __shfl_xor_sync(0xffffffffu, rs, 2);
            lr[h] = lr[h]*alpha + rs;
            #pragma unroll
            for (int n=0;n<8;n++) { o[n][h*2] *= alpha; o[n][h*2+1] *= alpha; }
        }

        // ---- O += P V ; P A-fragments via shuffle transpose of S C-fragments ----
        #pragma unroll
        for (int kf = 0; kf < 8; kf++) {
            float e0 = __shfl_sync(0xffffffffu, s[kf][0], src0);
            float e1 = __shfl_sync(0xffffffffu, s[kf][1], src0);
            float e2 = __shfl_sync(0xffffffffu, s[kf][2], src0);
            float e3 = __shfl_sync(0xffffffffu, s[kf][3], src0);
            float f0 = __shfl_sync(0xffffffffu, s[kf][0], src0 + 2);
            float f1 = __shfl_sync(0xffffffffu, s[kf][1], src0 + 2);
            float f2 = __shfl_sync(0xffffffffu, s[kf][2], src0 + 2);
            float f3 = __shfl_sync(0xffffffffu, s[kf][3], src0 + 2);
            uint32_t a[4];
            a[0] = f2tf(odd ? e1 : e0);
            a[1] = f2tf(odd ? e3 : e2);
            a[2] = f2tf(odd ? f1 : f0);
            a[3] = f2tf(odd ? f3 : f2);
            #pragma unroll
            for (int n = 0; n < 8; n++) {
                uint32_t b[2];
                const uint32_t* vp = Vs + (kf*8 + c)*TST + n*8 + g;
                b[0] = vp[0];
                b[1] = vp[4*TST];
                mma8(o[n], a, b);
            }
        }
        __syncthreads();   // compute done before next issue overwrites buffer
    }

    // ---- finalize: normalize and write concat layout [b][s][h*64+d] ----
    const int b = bh >> 3, hd = bh & 7;
    #pragma unroll
    for (int h = 0; h < 2; h++) {
        float inv = 1.f / lr[h];
        int row = qt*128 + wm + g + h*8;
        float* op = g_O + ((size_t)(b*SS + row))*DM + hd*DK;
        #pragma unroll
        for (int n=0;n<8;n++) {
            float2 v = { o[n][h*2]*inv, o[n][h*2+1]*inv };
            *(float2*)(op + n*8 + 2*c) = v;
        }
    }
}

extern "C" void kernel_launch(void* const* d_in, const int* in_sizes, int n_in,
                              void* d_out, int out_size) {
    const float* x  = (const float*)d_in[0];
    const float* Wq = (const float*)d_in[1];
    const float* Wk = (const float*)d_in[2];
    const float* Wv = (const float*)d_in[3];
    const float* Wo = (const float*)d_in[4];
    float* out = (float*)d_out;
    (void)in_sizes; (void)n_in; (void)out_size;

    static const int ATTN_SMEM = SMW_TOTAL * 4;  // 69632 bytes
    cudaFuncSetAttribute(attn_kernel, cudaFuncAttributeMaxDynamicSharedMemorySize, ATTN_SMEM);

    qkv_kernel<<<dim3(12, 64), 256>>>(x, Wq, Wk, Wv);
    attn_kernel<<<dim3(32, 16), 256, ATTN_SMEM>>>();
    oproj_kernel<<<dim3(4, 64), 256>>>(Wo, out);
}

// round 5
// speedup vs baseline: 1.8040x; 1.8040x over previous
#include <cuda_runtime.h>
#include <cuda_fp16.h>
#include <cstdint>

#define SS 4096
#define DK 64
#define DM 512
#define HH 8
#define BB 2
#define BH 16

// Scratch (static device globals — no runtime allocation)
__device__ __half g_Qh[BH*SS*DK];   // [bh][s][d], pre-scaled by log2(e)/8
__device__ __half g_Kh[BH*SS*DK];   // [bh][s][d]
__device__ __half g_Vh[BH*SS*DK];   // [bh][d][s]  (TRANSPOSED for B-fragment loads)
__device__ float  g_O [BB*SS*DM];   // fp32 attention output (concat layout)

__device__ __forceinline__ uint32_t f2tf(float f) {
    uint32_t u; asm("cvt.rna.tf32.f32 %0, %1;" : "=r"(u) : "f"(f)); return u;
}
__device__ __forceinline__ uint32_t pack_half2(float lo, float hi) {
    uint32_t u; asm("cvt.rn.f16x2.f32 %0, %1, %2;" : "=r"(u) : "f"(hi), "f"(lo)); return u;
}
__device__ __forceinline__ float ex2(float x) {
    float y; asm("ex2.approx.ftz.f32 %0, %1;" : "=f"(y) : "f"(x)); return y;
}

// tf32: D += A(16x8) * B(8x8)
__device__ __forceinline__ void mma8(float* d, const uint32_t* a, const uint32_t* b) {
    asm volatile("mma.sync.aligned.m16n8k8.row.col.f32.tf32.tf32.f32 "
        "{%0,%1,%2,%3}, {%4,%5,%6,%7}, {%8,%9}, {%0,%1,%2,%3};"
        : "+f"(d[0]), "+f"(d[1]), "+f"(d[2]), "+f"(d[3])
        : "r"(a[0]), "r"(a[1]), "r"(a[2]), "r"(a[3]), "r"(b[0]), "r"(b[1]));
}
// fp16: D += A(16x16) * B(16x8), f32 accum
__device__ __forceinline__ void mma16(float* d, const uint32_t* a, const uint32_t* b) {
    asm volatile("mma.sync.aligned.m16n8k16.row.col.f32.f16.f16.f32 "
        "{%0,%1,%2,%3}, {%4,%5,%6,%7}, {%8,%9}, {%0,%1,%2,%3};"
        : "+f"(d[0]), "+f"(d[1]), "+f"(d[2]), "+f"(d[3])
        : "r"(a[0]), "r"(a[1]), "r"(a[2]), "r"(a[3]), "r"(b[0]), "r"(b[1]));
}
__device__ __forceinline__ void cpa16(uint32_t dst, const void* src) {
    asm volatile("cp.async.cg.shared.global [%0], [%1], 16;" :: "r"(dst), "l"(src));
}

// ================= Projection GEMM: 128x128x16, 256 thr, warp tile 64x32 =================
#define PBM 128
#define PBN 128
#define PBK 16
#define AST 20
#define BST 136

__global__ __launch_bounds__(256) void qkv_kernel(const float* __restrict__ X,
                                                  const float* __restrict__ Wq,
                                                  const float* __restrict__ Wk,
                                                  const float* __restrict__ Wv)
{
    __shared__ uint32_t As[PBM*AST];
    __shared__ uint32_t Bs[PBK*BST];
    const int tid = threadIdx.x;
    const int nb = blockIdx.x, mb = blockIdx.y;
    const int proj = nb >> 2;
    const float* W = (proj==0) ? Wq : (proj==1) ? Wk : Wv;
    const int cb = (nb & 3) * PBN;

    const int warp = tid >> 5, lane = tid & 31;
    const int g = lane >> 2, c = lane & 3;
    const int wm = (warp & 1) * 64, wn = (warp >> 1) * 32;

    float acc[4][4][4];
    #pragma unroll
    for (int i=0;i<4;i++)
        #pragma unroll
        for (int j=0;j<4;j++)
            #pragma unroll
            for (int k=0;k<4;k++) acc[i][j][k] = 0.f;

    const int la_row = tid >> 1,  la_c = (tid & 1) * 8;
    const int lb_row = tid >> 4,  lb_c = (tid & 15) * 8;
    const float* Ap = X + (size_t)(mb*PBM + la_row)*DM + la_c;
    const float* Bp = W + (size_t)lb_row*DM + cb + lb_c;

    float4 ra0 = *(const float4*)(Ap);
    float4 ra1 = *(const float4*)(Ap + 4);
    float4 rb0 = *(const float4*)(Bp);
    float4 rb1 = *(const float4*)(Bp + 4);

    for (int k0 = 0; k0 < DM; k0 += PBK) {
        uint32_t* as = As + la_row*AST + la_c;
        as[0]=f2tf(ra0.x); as[1]=f2tf(ra0.y); as[2]=f2tf(ra0.z); as[3]=f2tf(ra0.w);
        as[4]=f2tf(ra1.x); as[5]=f2tf(ra1.y); as[6]=f2tf(ra1.z); as[7]=f2tf(ra1.w);
        uint32_t* bs = Bs + lb_row*BST + lb_c;
        bs[0]=f2tf(rb0.x); bs[1]=f2tf(rb0.y); bs[2]=f2tf(rb0.z); bs[3]=f2tf(rb0.w);
        bs[4]=f2tf(rb1.x); bs[5]=f2tf(rb1.y); bs[6]=f2tf(rb1.z); bs[7]=f2tf(rb1.w);
        __syncthreads();
        if (k0 + PBK < DM) {
            ra0 = *(const float4*)(Ap + k0 + PBK);
            ra1 = *(const float4*)(Ap + k0 + PBK + 4);
            rb0 = *(const float4*)(Bp + (size_t)(k0+PBK)*DM);
            rb1 = *(const float4*)(Bp + (size_t)(k0+PBK)*DM + 4);
        }
        #pragma unroll
        for (int ks = 0; ks < 2; ks++) {
            uint32_t a[4][4];
            #pragma unroll
            for (int mi=0; mi<4; mi++) {
                const uint32_t* ap = As + (wm + mi*16 + g)*AST + ks*8 + c;
                a[mi][0] = ap[0];
                a[mi][1] = ap[8*AST];
                a[mi][2] = ap[4];
                a[mi][3] = ap[8*AST + 4];
            }
            #pragma unroll
            for (int ni=0; ni<4; ni++) {
                uint32_t b[2];
                const uint32_t* bp = Bs + (ks*8 + c)*BST + wn + ni*8 + g;
                b[0] = bp[0];
                b[1] = bp[4*BST];
                #pragma unroll
                for (int mi=0; mi<4; mi++) mma8(acc[mi][ni], a[mi], b);
            }
        }
        __syncthreads();
    }

    // Q gets 1/8 (softmax scale) * log2(e) folded in (attention in exp2 domain)
    const float qscale = (proj == 0) ? 0.125f * 1.44269504088896f : 1.0f;
    #pragma unroll
    for (int mi=0; mi<4; mi++) {
        #pragma unroll
        for (int h=0; h<2; h++) {
            int gm = mb*PBM + wm + mi*16 + g + h*8;
            int b = gm >> 12, s = gm & (SS-1);
            #pragma unroll
            for (int ni=0; ni<4; ni++) {
                int wc = cb + wn + ni*8 + 2*c;
                int hd = wc >> 6, d = wc & 63;
                float v0 = acc[mi][ni][h*2+0];
                float v1 = acc[mi][ni][h*2+1];
                if (proj == 2) {
                    // V transposed: [bh][d][s]
                    __half* o = g_Vh + ((size_t)(b*HH + hd)*DK + d)*SS + s;
                    o[0]  = __float2half_rn(v0);
                    o[SS] = __float2half_rn(v1);
                } else {
                    __half* OutB = (proj == 0) ? g_Qh : g_Kh;
                    uint32_t p = pack_half2(v0*qscale, v1*qscale);
                    *(uint32_t*)(OutB + (((size_t)(b*HH + hd)*SS) + s)*DK + d) = p;
                }
            }
        }
    }
}

__global__ __launch_bounds__(256) void oproj_kernel(const float* __restrict__ Wo,
                                                    float* __restrict__ Out)
{
    __shared__ uint32_t As[PBM*AST];
    __shared__ uint32_t Bs[PBK*BST];
    const int tid = threadIdx.x;
    const int nb = blockIdx.x, mb = blockIdx.y;
    const int cb = nb * PBN;

    const int warp = tid >> 5, lane = tid & 31;
    const int g = lane >> 2, c = lane & 3;
    const int wm = (warp & 1) * 64, wn = (warp >> 1) * 32;

    float acc[4][4][4];
    #pragma unroll
    for (int i=0;i<4;i++)
        #pragma unroll
        for (int j=0;j<4;j++)
            #pragma unroll
            for (int k=0;k<4;k++) acc[i][j][k] = 0.f;

    const int la_row = tid >> 1,  la_c = (tid & 1) * 8;
    const int lb_row = tid >> 4,  lb_c = (tid & 15) * 8;
    const float* Ap = g_O + (size_t)(mb*PBM + la_row)*DM + la_c;
    const float* Bp = Wo + (size_t)lb_row*DM + cb + lb_c;

    float4 ra0 = *(const float4*)(Ap);
    float4 ra1 = *(const float4*)(Ap + 4);
    float4 rb0 = *(const float4*)(Bp);
    float4 rb1 = *(const float4*)(Bp + 4);

    for (int k0 = 0; k0 < DM; k0 += PBK) {
        uint32_t* as = As + la_row*AST + la_c;
        as[0]=f2tf(ra0.x); as[1]=f2tf(ra0.y); as[2]=f2tf(ra0.z); as[3]=f2tf(ra0.w);
        as[4]=f2tf(ra1.x); as[5]=f2tf(ra1.y); as[6]=f2tf(ra1.z); as[7]=f2tf(ra1.w);
        uint32_t* bs = Bs + lb_row*BST + lb_c;
        bs[0]=f2tf(rb0.x); bs[1]=f2tf(rb0.y); bs[2]=f2tf(rb0.z); bs[3]=f2tf(rb0.w);
        bs[4]=f2tf(rb1.x); bs[5]=f2tf(rb1.y); bs[6]=f2tf(rb1.z); bs[7]=f2tf(rb1.w);
        __syncthreads();
        if (k0 + PBK < DM) {
            ra0 = *(const float4*)(Ap + k0 + PBK);
            ra1 = *(const float4*)(Ap + k0 + PBK + 4);
            rb0 = *(const float4*)(Bp + (size_t)(k0+PBK)*DM);
            rb1 = *(const float4*)(Bp + (size_t)(k0+PBK)*DM + 4);
        }
        #pragma unroll
        for (int ks = 0; ks < 2; ks++) {
            uint32_t a[4][4];
            #pragma unroll
            for (int mi=0; mi<4; mi++) {
                const uint32_t* ap = As + (wm + mi*16 + g)*AST + ks*8 + c;
                a[mi][0] = ap[0];
                a[mi][1] = ap[8*AST];
                a[mi][2] = ap[4];
                a[mi][3] = ap[8*AST + 4];
            }
            #pragma unroll
            for (int ni=0; ni<4; ni++) {
                uint32_t b[2];
                const uint32_t* bp = Bs + (ks*8 + c)*BST + wn + ni*8 + g;
                b[0] = bp[0];
                b[1] = bp[4*BST];
                #pragma unroll
                for (int mi=0; mi<4; mi++) mma8(acc[mi][ni], a[mi], b);
            }
        }
        __syncthreads();
    }

    #pragma unroll
    for (int mi=0; mi<4; mi++) {
        #pragma unroll
        for (int h=0; h<2; h++) {
            int gm = mb*PBM + wm + mi*16 + g + h*8;
            #pragma unroll
            for (int ni=0; ni<4; ni++) {
                float2 v = { acc[mi][ni][h*2+0], acc[mi][ni][h*2+1] };
                *(float2*)(Out + (size_t)gm*DM + cb + wn + ni*8 + 2*c) = v;
            }
        }
    }
}

// ================= Flash attention v3: fp16 MMA, zero-shuffle P, cp.async dbl-buffer =====
#define KSTH 72                  // row stride in halves (144B) -> banks 4g+c, conflict-free
#define TILE_H (64*KSTH)         // halves per K or V buffer (4608)
#define SMH_TOTAL (4*TILE_H)     // K0,K1,V0,V1 = 18432 halves = 36864 bytes

__global__ __launch_bounds__(256, 2) void attn_kernel()
{
    extern __shared__ __half smh[];
    const int tid = threadIdx.x;
    const int warp = tid >> 5, lane = tid & 31;
    const int g = lane >> 2, c = lane & 3;
    const int wm = warp * 16;
    const int qt = blockIdx.x;   // 0..31
    const int bh = blockIdx.y;   // 0..15

    const __half* Qg = g_Qh + ((size_t)bh*SS + qt*128)*DK;
    const __half* Kg = g_Kh + (size_t)bh*SS*DK;
    const __half* Vg = g_Vh + (size_t)bh*DK*SS;

    // ---- stage Q (128x64 fp16) through smem, pull A-fragments into registers ----
    #pragma unroll
    for (int i = 0; i < 4; i++) {
        int e = tid + i*256;
        int row = e >> 3, ch = e & 7;
        *(uint4*)(smh + row*KSTH + ch*8) = *(const uint4*)(Qg + (size_t)row*DK + ch*8);
    }
    __syncthreads();
    uint32_t q[4][4];
    #pragma unroll
    for (int t = 0; t < 4; t++) {
        q[t][0] = *(const uint32_t*)(smh + (wm+g  )*KSTH + t*16 + 2*c);
        q[t][1] = *(const uint32_t*)(smh + (wm+g+8)*KSTH + t*16 + 2*c);
        q[t][2] = *(const uint32_t*)(smh + (wm+g  )*KSTH + t*16 + 2*c + 8);
        q[t][3] = *(const uint32_t*)(smh + (wm+g+8)*KSTH + t*16 + 2*c + 8);
    }
    __syncthreads();

    uint32_t sb = (uint32_t)__cvta_generic_to_shared(smh);
    const int l_row = tid >> 3, l_ch = tid & 7;   // 32 rows x 8 chunks per 256-thr pass

    auto issue = [&](int kt, int b) {
        uint32_t kdst = sb + (uint32_t)(b*TILE_H)*2;
        uint32_t vdst = sb + (uint32_t)((2+b)*TILE_H)*2;
        #pragma unroll
        for (int i = 0; i < 2; i++) {
            int row = l_row + i*32;
            cpa16(kdst + (uint32_t)(row*KSTH + l_ch*8)*2,
                  Kg + (size_t)(kt*64 + row)*DK + l_ch*8);
            cpa16(vdst + (uint32_t)(row*KSTH + l_ch*8)*2,
                  Vg + (size_t)row*SS + kt*64 + l_ch*8);
        }
        asm volatile("cp.async.commit_group;" ::: "memory");
    };

    issue(0, 0);

    float o[8][4];
    float mr[2] = {-1e30f, -1e30f}, lr[2] = {0.f, 0.f};
    #pragma unroll
    for (int n=0;n<8;n++)
        #pragma unroll
        for (int k=0;k<4;k++) o[n][k]=0.f;

    for (int kt = 0; kt < SS/64; kt++) {
        const int cur = kt & 1;
        if (kt < SS/64 - 1) {
            issue(kt+1, cur^1);
            asm volatile("cp.async.wait_group 1;" ::: "memory");
        } else {
            asm volatile("cp.async.wait_group 0;" ::: "memory");
        }
        __syncthreads();

        const __half* Ksm = smh + cur*TILE_H;
        const __half* Vsm = smh + (2+cur)*TILE_H;

        // ---- S = Q K^T (fp16 mma, log2 domain, Q pre-scaled) ----
        float s[8][4];
        #pragma unroll
        for (int n=0;n<8;n++)
            #pragma unroll
            for (int k=0;k<4;k++) s[n][k]=0.f;

        #pragma unroll
        for (int t = 0; t < 4; t++) {
            #pragma unroll
            for (int n = 0; n < 8; n++) {
                uint32_t b[2];
                const __half* kp = Ksm + (n*8 + g)*KSTH + t*16 + 2*c;
                b[0] = *(const uint32_t*)(kp);
                b[1] = *(const uint32_t*)(kp + 8);
                mma16(s[n], q[t], b);
            }
        }

        // ---- online softmax (exp2 domain) ----
        #pragma unroll
        for (int h = 0; h < 2; h++) {
            float mx = -1e30f;
            #pragma unroll
            for (int n=0;n<8;n++) mx = fmaxf(mx, fmaxf(s[n][h*2], s[n][h*2+1]));
            mx = fmaxf(mx, __shfl_xor_sync(0xffffffffu, mx, 1));
            mx = fmaxf(mx, __shfl_xor_sync(0xffffffffu, mx, 2));
            float mnew = fmaxf(mr[h], mx);
            float alpha = ex2(mr[h] - mnew);
            mr[h] = mnew;
            float rs = 0.f;
            #pragma unroll
            for (int n=0;n<8;n++) {
                float p0 = ex2(s[n][h*2]   - mnew);
                float p1 = ex2(s[n][h*2+1] - mnew);
                s[n][h*2] = p0; s[n][h*2+1] = p1;
                rs += p0 + p1;
            }
            rs += __shfl_xor_sync(0xffffffffu, rs, 1);
            rs += __shfl_xor_sync(0xffffffffu, rs, 2);
            lr[h] = lr[h]*alpha + rs;
            #pragma unroll
            for (int n=0;n<8;n++) { o[n][h*2] *= alpha; o[n][h*2+1] *= alpha; }
        }

        // ---- O += P V : C-fragment pairs ARE fp16 A-fragment halves (zero shuffles) ----
        #pragma unroll
        for (int t = 0; t < 4; t++) {
            uint32_t a[4];
            a[0] = pack_half2(s[2*t  ][0], s[2*t  ][1]);
            a[1] = pack_half2(s[2*t  ][2], s[2*t  ][3]);
            a[2] = pack_half2(s[2*t+1][0], s[2*t+1][1]);
            a[3] = pack_half2(s[2*t+1][2], s[2*t+1][3]);
            #pragma unroll
            for (int n = 0; n < 8; n++) {
                uint32_t b[2];
                const __half* vp = Vsm + (n*8 + g)*KSTH + t*16 + 2*c;
                b[0] = *(const uint32_t*)(vp);
                b[1] = *(const uint32_t*)(vp + 8);
                mma16(o[n], a, b);
            }
        }
        __syncthreads();
    }

    // ---- finalize: normalize and write concat layout [b][s][h*64+d] ----
    const int b = bh >> 3, hd = bh & 7;
    #pragma unroll
    for (int h = 0; h < 2; h++) {
        float inv = 1.f / lr[h];
        int row = qt*128 + wm + g + h*8;
        float* op = g_O + ((size_t)(b*SS + row))*DM + hd*DK;
        #pragma unroll
        for (int n=0;n<8;n++) {
            float2 v = { o[n][h*2]*inv, o[n][h*2+1]*inv };
            *(float2*)(op + n*8 + 2*c) = v;
        }
    }
}

extern "C" void kernel_launch(void* const* d_in, const int* in_sizes, int n_in,
                              void* d_out, int out_size) {
    const float* x  = (const float*)d_in[0];
    const float* Wq = (const float*)d_in[1];
    const float* Wk = (const float*)d_in[2];
    const float* Wv = (const float*)d_in[3];
    const float* Wo = (const float*)d_in[4];
    float* out = (float*)d_out;
    (void)in_sizes; (void)n_in; (void)out_size;

    static const int ATTN_SMEM = SMH_TOTAL * 2;  // 36864 bytes
    qkv_kernel<<<dim3(12, 64), 256>>>(x, Wq, Wk, Wv);
    attn_kernel<<<dim3(32, 16), 256, ATTN_SMEM>>>();
    oproj_kernel<<<dim3(4, 64), 256>>>(Wo, out);
}

// round 8
// speedup vs baseline: 2.3007x; 1.2753x over previous
#include <cuda_runtime.h>
#include <cuda_fp16.h>
#include <cstdint>

#define SS 4096
#define DK 64
#define DM 512
#define HH 8
#define BB 2
#define BH 16

// Scratch (static device globals — no runtime allocation)
__device__ __half g_Xh[BB*SS*DM];    // x converted to fp16 [m][k]
__device__ __half g_WT[4*DM*DM];     // Wq,Wk,Wv,Wo transposed to [n][k] fp16
__device__ __half g_Qh[BH*SS*DK];    // [bh][s][d], pre-scaled by log2(e)/8
__device__ __half g_Kh[BH*SS*DK];    // [bh][s][d]
__device__ __half g_Vh[BH*SS*DK];    // [bh][d][s]  (transposed for B-frag loads)
__device__ __half g_Oh[BB*SS*DM];    // attention output fp16 (concat layout)

__device__ __forceinline__ uint32_t pack_half2(float lo, float hi) {
    uint32_t u; asm("cvt.rn.f16x2.f32 %0, %1, %2;" : "=r"(u) : "f"(hi), "f"(lo)); return u;
}
__device__ __forceinline__ float ex2(float x) {
    float y; asm("ex2.approx.ftz.f32 %0, %1;" : "=f"(y) : "f"(x)); return y;
}
// fp16: D += A(16x16) * B(16x8), f32 accum
__device__ __forceinline__ void mma16(float* d, const uint32_t* a, const uint32_t* b) {
    asm volatile("mma.sync.aligned.m16n8k16.row.col.f32.f16.f16.f32 "
        "{%0,%1,%2,%3}, {%4,%5,%6,%7}, {%8,%9}, {%0,%1,%2,%3};"
        : "+f"(d[0]), "+f"(d[1]), "+f"(d[2]), "+f"(d[3])
        : "r"(a[0]), "r"(a[1]), "r"(a[2]), "r"(a[3]), "r"(b[0]), "r"(b[1]));
}
__device__ __forceinline__ void cpa16(uint32_t dst, const void* src) {
    asm volatile("cp.async.cg.shared.global [%0], [%1], 16;" :: "r"(dst), "l"(src));
}

// ================= converters =================
__global__ __launch_bounds__(256) void convx_kernel(const float* __restrict__ X) {
    size_t i = ((size_t)blockIdx.x*256 + threadIdx.x) * 8;
    float4 v0 = *(const float4*)(X + i);
    float4 v1 = *(const float4*)(X + i + 4);
    uint4 p;
    p.x = pack_half2(v0.x, v0.y); p.y = pack_half2(v0.z, v0.w);
    p.z = pack_half2(v1.x, v1.y); p.w = pack_half2(v1.z, v1.w);
    *(uint4*)(g_Xh + i) = p;
}

// transpose+convert weights: g_WT[w][n][k] = W_w[k][n]
__global__ __launch_bounds__(256) void convw_kernel(const float* __restrict__ Wq,
                                                    const float* __restrict__ Wk,
                                                    const float* __restrict__ Wv,
                                                    const float* __restrict__ Wo) {
    __shared__ float t[32][33];
    const int w = blockIdx.z;
    const float* W = (w==0) ? Wq : (w==1) ? Wk : (w==2) ? Wv : Wo;
    __half* out = g_WT + (size_t)w*DM*DM;
    const int tx = threadIdx.x & 31, ty = threadIdx.x >> 5;   // 32 x 8
    const int bx = blockIdx.x * 32, by = blockIdx.y * 32;     // bx: n, by: k
    #pragma unroll
    for (int j = 0; j < 32; j += 8)
        t[ty+j][tx] = W[(size_t)(by+ty+j)*DM + bx+tx];
    __syncthreads();
    #pragma unroll
    for (int j = 0; j < 32; j += 8)
        out[(size_t)(bx+ty+j)*DM + by+tx] = __float2half_rn(t[tx][ty+j]);
}

// ================= fp16 GEMM: 128x128x32, 3-stage cp.async, 8 warps x (64x32) ===========
#define GBM 128
#define GBN 128
#define GBK 32
#define GAST 40                       // row stride in halves (80B) -> frag loads conflict-free
#define STG_A (GBM*GAST)              // 5120 halves
#define STG_H ((GBM+GBN)*GAST)        // 10240 halves per stage
#define GSM_TOTAL (3*STG_H)           // 30720 halves = 61440 bytes

// mode: -1 => qkv from g_Xh (proj from blockIdx.x>>2); 3 => oproj from g_Oh -> Out (fp32)
__global__ __launch_bounds__(256) void gemm16_kernel(float* __restrict__ Out, int mode)
{
    extern __shared__ __half gsm[];
    const int tid = threadIdx.x;
    const int warp = tid >> 5, lane = tid & 31;
    const int g = lane >> 2, c = lane & 3;
    const int wm = (warp & 1) * 64, wn = (warp >> 1) * 32;
    const int mb = blockIdx.y;

    int proj, cb;
    const __half* A;
    if (mode < 0) { proj = blockIdx.x >> 2; cb = (blockIdx.x & 3) * GBN; A = g_Xh; }
    else          { proj = 3;               cb = blockIdx.x * GBN;       A = g_Oh; }
    const __half* Bp = g_WT + (size_t)proj*DM*DM;

    float acc[4][4][4];
    #pragma unroll
    for (int i=0;i<4;i++)
        #pragma unroll
        for (int j=0;j<4;j++)
            #pragma unroll
            for (int k=0;k<4;k++) acc[i][j][k] = 0.f;

    uint32_t sb = (uint32_t)__cvta_generic_to_shared(gsm);
    const int ar = tid >> 1;                 // 0..127 (row for both A and B tiles)
    const int ac = (tid & 1) * 2;            // chunk pair base (2 of 4 chunks of 8 halves)

    const __half* Ag = A  + (size_t)(mb*GBM + ar)*DM;
    const __half* Bg = Bp + (size_t)(cb + ar)*DM;

    auto issue = [&](int slab, int stg) {
        uint32_t ab = sb + (uint32_t)(stg*STG_H)*2;
        uint32_t bb = ab + (uint32_t)STG_A*2;
        int k0 = slab * GBK;
        #pragma unroll
        for (int i = 0; i < 2; i++) {
            int ch = ac + i;
            cpa16(ab + (uint32_t)(ar*GAST + ch*8)*2, Ag + k0 + ch*8);
            cpa16(bb + (uint32_t)(ar*GAST + ch*8)*2, Bg + k0 + ch*8);
        }
        asm volatile("cp.async.commit_group;" ::: "memory");
    };

    issue(0, 0);
    issue(1, 1);

    const int NSLAB = DM / GBK;   // 16
    for (int slab = 0; slab < NSLAB; slab++) {
        const int stg = slab % 3;
        if (slab + 2 < NSLAB) {
            issue(slab + 2, (slab + 2) % 3);
            asm volatile("cp.async.wait_group 2;" ::: "memory");
        } else if (slab + 1 < NSLAB) {
            asm volatile("cp.async.wait_group 1;" ::: "memory");
        } else {
            asm volatile("cp.async.wait_group 0;" ::: "memory");
        }
        __syncthreads();

        const __half* As_ = gsm + stg*STG_H;
        const __half* Bs_ = As_ + STG_A;

        #pragma unroll
        for (int ks = 0; ks < 2; ks++) {
            uint32_t a[4][4];
            #pragma unroll
            for (int mi = 0; mi < 4; mi++) {
                const __half* ap = As_ + (wm + mi*16 + g)*GAST + ks*16 + 2*c;
                a[mi][0] = *(const uint32_t*)(ap);
                a[mi][1] = *(const uint32_t*)(ap + 8*GAST);
                a[mi][2] = *(const uint32_t*)(ap + 8);
                a[mi][3] = *(const uint32_t*)(ap + 8*GAST + 8);
            }
            #pragma unroll
            for (int ni = 0; ni < 4; ni++) {
                uint32_t b[2];
                const __half* bp = Bs_ + (wn + ni*8 + g)*GAST + ks*16 + 2*c;
                b[0] = *(const uint32_t*)(bp);
                b[1] = *(const uint32_t*)(bp + 8);
                #pragma unroll
                for (int mi = 0; mi < 4; mi++) mma16(acc[mi][ni], a[mi], b);
            }
        }
        __syncthreads();
    }

    // ---- epilogue ----
    if (proj == 3) {
        // output projection: fp32 to d_out
        #pragma unroll
        for (int mi = 0; mi < 4; mi++)
            #pragma unroll
            for (int h = 0; h < 2; h++) {
                int gm = mb*GBM + wm + mi*16 + g + h*8;
                #pragma unroll
                for (int ni = 0; ni < 4; ni++) {
                    float2 v = { acc[mi][ni][h*2+0], acc[mi][ni][h*2+1] };
                    *(float2*)(Out + (size_t)gm*DM + cb + wn + ni*8 + 2*c) = v;
                }
            }
    } else {
        const float qscale = (proj == 0) ? 0.125f * 1.44269504088896f : 1.0f;
        #pragma unroll
        for (int mi = 0; mi < 4; mi++)
            #pragma unroll
            for (int h = 0; h < 2; h++) {
                int gm = mb*GBM + wm + mi*16 + g + h*8;
                int b = gm >> 12, s = gm & (SS-1);
                #pragma unroll
                for (int ni = 0; ni < 4; ni++) {
                    int wc = cb + wn + ni*8 + 2*c;
                    int hd = wc >> 6, d = wc & 63;
                    float v0 = acc[mi][ni][h*2+0];
                    float v1 = acc[mi][ni][h*2+1];
                    if (proj == 2) {
                        __half* o = g_Vh + ((size_t)(b*HH + hd)*DK + d)*SS + s;
                        o[0]  = __float2half_rn(v0);
                        o[SS] = __float2half_rn(v1);
                    } else {
                        __half* OutB = (proj == 0) ? g_Qh : g_Kh;
                        *(uint32_t*)(OutB + (((size_t)(b*HH + hd)*SS) + s)*DK + d)
                            = pack_half2(v0*qscale, v1*qscale);
                    }
                }
            }
    }
}

// ================= Flash attention: fp16 MMA, zero-shuffle P, cp.async dbl-buffer =====
#define KSTH 72                  // row stride in halves -> banks 4g+c, conflict-free
#define TILE_H (64*KSTH)
#define SMH_TOTAL (4*TILE_H)     // 36864 bytes

__global__ __launch_bounds__(256, 2) void attn_kernel()
{
    extern __shared__ __half smh[];
    const int tid = threadIdx.x;
    const int warp = tid >> 5, lane = tid & 31;
    const int g = lane >> 2, c = lane & 3;
    const int wm = warp * 16;
    const int qt = blockIdx.x;   // 0..31
    const int bh = blockIdx.y;   // 0..15

    const __half* Qg = g_Qh + ((size_t)bh*SS + qt*128)*DK;
    const __half* Kg = g_Kh + (size_t)bh*SS*DK;
    const __half* Vg = g_Vh + (size_t)bh*DK*SS;

    // stage Q through smem, pull A-fragments into registers
    #pragma unroll
    for (int i = 0; i < 4; i++) {
        int e = tid + i*256;
        int row = e >> 3, ch = e & 7;
        *(uint4*)(smh + row*KSTH + ch*8) = *(const uint4*)(Qg + (size_t)row*DK + ch*8);
    }
    __syncthreads();
    uint32_t q[4][4];
    #pragma unroll
    for (int t = 0; t < 4; t++) {
        q[t][0] = *(const uint32_t*)(smh + (wm+g  )*KSTH + t*16 + 2*c);
        q[t][1] = *(const uint32_t*)(smh + (wm+g+8)*KSTH + t*16 + 2*c);
        q[t][2] = *(const uint32_t*)(smh + (wm+g  )*KSTH + t*16 + 2*c + 8);
        q[t][3] = *(const uint32_t*)(smh + (wm+g+8)*KSTH + t*16 + 2*c + 8);
    }
    __syncthreads();

    uint32_t sb = (uint32_t)__cvta_generic_to_shared(smh);
    const int l_row = tid >> 3, l_ch = tid & 7;

    auto issue = [&](int kt, int b) {
        uint32_t kdst = sb + (uint32_t)(b*TILE_H)*2;
        uint32_t vdst = sb + (uint32_t)((2+b)*TILE_H)*2;
        #pragma unroll
        for (int i = 0; i < 2; i++) {
            int row = l_row + i*32;
            cpa16(kdst + (uint32_t)(row*KSTH + l_ch*8)*2,
                  Kg + (size_t)(kt*64 + row)*DK + l_ch*8);
            cpa16(vdst + (uint32_t)(row*KSTH + l_ch*8)*2,
                  Vg + (size_t)row*SS + kt*64 + l_ch*8);
        }
        asm volatile("cp.async.commit_group;" ::: "memory");
    };

    issue(0, 0);

    float o[8][4];
    float mr[2] = {-1e30f, -1e30f}, lr[2] = {0.f, 0.f};
    #pragma unroll
    for (int n=0;n<8;n++)
        #pragma unroll
        for (int k=0;k<4;k++) o[n][k]=0.f;

    for (int kt = 0; kt < SS/64; kt++) {
        const int cur = kt & 1;
        if (kt < SS/64 - 1) {
            issue(kt+1, cur^1);
            asm volatile("cp.async.wait_group 1;" ::: "memory");
        } else {
            asm volatile("cp.async.wait_group 0;" ::: "memory");
        }
        __syncthreads();

        const __half* Ksm = smh + cur*TILE_H;
        const __half* Vsm = smh + (2+cur)*TILE_H;

        float s[8][4];
        #pragma unroll
        for (int n=0;n<8;n++)
            #pragma unroll
            for (int k=0;k<4;k++) s[n][k]=0.f;

        #pragma unroll
        for (int t = 0; t < 4; t++) {
            #pragma unroll
            for (int n = 0; n < 8; n++) {
                uint32_t b[2];
                const __half* kp = Ksm + (n*8 + g)*KSTH + t*16 + 2*c;
                b[0] = *(const uint32_t*)(kp);
                b[1] = *(const uint32_t*)(kp + 8);
                mma16(s[n], q[t], b);
            }
        }

        #pragma unroll
        for (int h = 0; h < 2; h++) {
            float mx = -1e30f;
            #pragma unroll
            for (int n=0;n<8;n++) mx = fmaxf(mx, fmaxf(s[n][h*2], s[n][h*2+1]));
            mx = fmaxf(mx, __shfl_xor_sync(0xffffffffu, mx, 1));
            mx = fmaxf(mx, __shfl_xor_sync(0xffffffffu, mx, 2));
            float mnew = fmaxf(mr[h], mx);
            float alpha = ex2(mr[h] - mnew);
            mr[h] = mnew;
            float rs = 0.f;
            #pragma unroll
            for (int n=0;n<8;n++) {
                float p0 = ex2(s[n][h*2]   - mnew);
                float p1 = ex2(s[n][h*2+1] - mnew);
                s[n][h*2] = p0; s[n][h*2+1] = p1;
                rs += p0 + p1;
            }
            rs += __shfl_xor_sync(0xffffffffu, rs, 1);
            rs += __shfl_xor_sync(0xffffffffu, rs, 2);
            lr[h] = lr[h]*alpha + rs;
            #pragma unroll
            for (int n=0;n<8;n++) { o[n][h*2] *= alpha; o[n][h*2+1] *= alpha; }
        }

        #pragma unroll
        for (int t = 0; t < 4; t++) {
            uint32_t a[4];
            a[0] = pack_half2(s[2*t  ][0], s[2*t  ][1]);
            a[1] = pack_half2(s[2*t  ][2], s[2*t  ][3]);
            a[2] = pack_half2(s[2*t+1][0], s[2*t+1][1]);
            a[3] = pack_half2(s[2*t+1][2], s[2*t+1][3]);
            #pragma unroll
            for (int n = 0; n < 8; n++) {
                uint32_t b[2];
                const __half* vp = Vsm + (n*8 + g)*KSTH + t*16 + 2*c;
                b[0] = *(const uint32_t*)(vp);
                b[1] = *(const uint32_t*)(vp + 8);
                mma16(o[n], a, b);
            }
        }
        __syncthreads();
    }

    // finalize: normalize, write fp16 concat layout [b][s][h*64+d]
    const int b = bh >> 3, hd = bh & 7;
    #pragma unroll
    for (int h = 0; h < 2; h++) {
        float inv = 1.f / lr[h];
        int row = qt*128 + wm + g + h*8;
        __half* op = g_Oh + ((size_t)(b*SS + row))*DM + hd*DK;
        #pragma unroll
        for (int n=0;n<8;n++)
            *(uint32_t*)(op + n*8 + 2*c) = pack_half2(o[n][h*2]*inv, o[n][h*2+1]*inv);
    }
}

extern "C" void kernel_launch(void* const* d_in, const int* in_sizes, int n_in,
                              void* d_out, int out_size) {
    const float* x  = (const float*)d_in[0];
    const float* Wq = (const float*)d_in[1];
    const float* Wk = (const float*)d_in[2];
    const float* Wv = (const float*)d_in[3];
    const float* Wo = (const float*)d_in[4];
    float* out = (float*)d_out;
    (void)in_sizes; (void)n_in; (void)out_size;

    static const int GEMM_SMEM = GSM_TOTAL * 2;  // 61440 bytes
    static const int ATTN_SMEM = SMH_TOTAL * 2;  // 36864 bytes
    cudaFuncSetAttribute(gemm16_kernel, cudaFuncAttributeMaxDynamicSharedMemorySize, GEMM_SMEM);

    convx_kernel<<<2048, 256>>>(x);
    convw_kernel<<<dim3(16, 16, 4), 256>>>(Wq, Wk, Wv, Wo);
    gemm16_kernel<<<dim3(12, 64), 256, GEMM_SMEM>>>(nullptr, -1);
    attn_kernel<<<dim3(32, 16), 256, ATTN_SMEM>>>();
    gemm16_kernel<<<dim3(4, 64), 256, GEMM_SMEM>>>(out, 3);
}